// round 17
// baseline (speedup 1.0000x reference)
#include <cuda_runtime.h>
#include <math.h>

// ---------------------------------------------------------------------------
// Butterfly module, round 17. SINGLE kernel launch.
//
// R13 (best, 49.9us) with ONE reg-neutral change: while loading slice 1,
// issue prefetch.global.L2 for the matching slice-2 lines (+2048B, same
// address register, no destination reg, no scoreboard slot). Slice-2 DRAM
// latency is absorbed during slice-1 compute; slice-2 LDGs hit L2 (~250cyc
// vs ~600). Registers and occupancy provably unchanged.
// ---------------------------------------------------------------------------

typedef unsigned long long u64;

#define CURV2_PK  0x3C23D70A3C23D70AULL   // (0.01f, 0.01f)
#define HALF_PK   0x3F0000003F000000ULL   // (0.5f, 0.5f)

__device__ __forceinline__ u64 pack2(float x, float y) {
    u64 r; asm("mov.b64 %0, {%1, %2};" : "=l"(r) : "f"(x), "f"(y)); return r;
}
__device__ __forceinline__ float2 unpack2(u64 v) {
    float2 r; asm("mov.b64 {%0, %1}, %2;" : "=f"(r.x), "=f"(r.y) : "l"(v)); return r;
}
__device__ __forceinline__ u64 fma2(u64 a, u64 b, u64 c) {
    u64 d; asm("fma.rn.f32x2 %0, %1, %2, %3;" : "=l"(d) : "l"(a), "l"(b), "l"(c));
    return d;
}
__device__ __forceinline__ u64 mul2(u64 a, u64 b) {
    u64 d; asm("mul.rn.f32x2 %0, %1, %2;" : "=l"(d) : "l"(a), "l"(b)); return d;
}
__device__ __forceinline__ u64 add2(u64 a, u64 b) {
    u64 d; asm("add.rn.f32x2 %0, %1, %2;" : "=l"(d) : "l"(a), "l"(b)); return d;
}
__device__ __forceinline__ u64 sub2(u64 a, u64 b) {
    u64 d; asm("sub.rn.f32x2 %0, %1, %2;" : "=l"(d) : "l"(a), "l"(b)); return d;
}

// Full 16-row butterfly layer, stride S; srot = 8 {c2,s2} pairs (asc. low).
template <int S>
__device__ __forceinline__ void blayer16(u64 a[16],
                                         const ulonglong2* __restrict__ srot) {
    int p = 0;
#pragma unroll
    for (int o = 0; o < 16; ++o) {
        if ((o & S) == 0) {
            ulonglong2 r = srot[p++];          // LDS.128: {c2, s2}
            u64 l = a[o], h = a[o + S];
            a[o]     = fma2(r.x, l, mul2(r.y, h));
            a[o + S] = sub2(mul2(r.x, h), mul2(r.y, l));
        }
    }
}

__global__ __launch_bounds__(256)
void butterfly_fused_kernel(const float* __restrict__ data,
                            const float* __restrict__ angles,
                            const float* __restrict__ biases,
                            const int*   __restrict__ idx_in,
                            const int*   __restrict__ idx_out,
                            float*       __restrict__ out,
                            int N, int B, int NB, int R)
{
    const int tid = threadIdx.x;
    const int by  = blockIdx.y;

    // ---------------- tail blocks: pass-through copy of uncovered rows ------
    if (by >= NB) {
        if (blockIdx.x != 0) return;          // one block per 16-row group
        __shared__ unsigned int covmask;
        const int base = (by - NB) * 16;
        if (tid == 0) covmask = 0;
        __syncthreads();
        for (int i = tid; i < N; i += 256) {
            int r = idx_out[i] - base;
            if ((unsigned)r < 16u) atomicOr(&covmask, 1u << r);
        }
        __syncthreads();
        unsigned int cm = covmask;
#pragma unroll 1
        for (int r = 0; r < 16; ++r) {
            int row = base + r;
            if (row >= R || (cm >> r) & 1u) continue;
            const float4* src = reinterpret_cast<const float4*>(data + (size_t)row * B);
            float4*       dst = reinterpret_cast<float4*>(out + (size_t)row * B);
            for (int i = tid; i < (B >> 2); i += blockDim.x)
                dst[i] = src[i];
        }
        return;
    }

    // ---------------- butterfly blocks --------------------------------------
    __shared__ ulonglong2 srot[64];   // [layer 0..7][pair 0..7] = {c2, s2}
    __shared__ u64 sb2[8];            // packed biases
    __shared__ int oin[16], oout[16]; // premultiplied row offsets (elements)

    const int blk = by;

    if (tid < 64) {
        int l = tid >> 3, p = tid & 7;
        float ang = angles[(size_t)l * (N >> 1) + blk * 8 + p];
        float s, c;
        __sincosf(ang, &s, &c);
        srot[tid].x = pack2(c, c);
        srot[tid].y = pack2(s, s);
    }
    if (tid < 8) {
        float b = biases[blk * 8 + tid];
        sb2[tid] = pack2(b, b);
    }
    if (tid < 16) {
        oin[tid]  = idx_in [blk * 16 + tid] * B;
        oout[tid] = idx_out[blk * 16 + tid] * B;
    }
    __syncthreads();

    const int col0 = blockIdx.x * 1024 + tid * 2;

#pragma unroll 1
    for (int sub = 0; sub < 2; ++sub) {
        const int col = col0 + sub * 512;

        // --- load 16 rows x f32x2; on slice 0 also prefetch slice 1 to L2 ---
        u64 a[16];
#pragma unroll
        for (int i = 0; i < 16; ++i) {
            const u64* p = reinterpret_cast<const u64*>(data + (size_t)(oin[i] + col));
            a[i] = __ldcs(p);
            if (sub == 0)
                asm volatile("prefetch.global.L2 [%0];" :: "l"(p + 256));
        }

        // --- input layers: strides 1,2,4,8 ---
        blayer16<1>(a, srot + 0);
        blayer16<2>(a, srot + 8);
        blayer16<4>(a, srot + 16);
        blayer16<8>(a, srot + 24);

        // --- fused bias + smooth relu on rows 0-7 ---
#pragma unroll
        for (int i = 0; i < 8; ++i) {
            u64 xa = add2(a[i], sb2[i]);
            u64 t  = fma2(xa, xa, CURV2_PK);          // xa^2 + curv^2  (>= 0.01)
            float2 tf = unpack2(t);
            float s0 = __frsqrt_rn(tf.x) * tf.x;      // sqrt(t) via MUFU
            float s1 = __frsqrt_rn(tf.y) * tf.y;
            a[i] = mul2(HALF_PK, add2(xa, pack2(s0, s1)));
        }

        // --- output layers: strides 1,2,4,8 ---
        blayer16<1>(a, srot + 32);
        blayer16<2>(a, srot + 40);
        blayer16<4>(a, srot + 48);
        blayer16<8>(a, srot + 56);

        // --- store (streaming) ---
#pragma unroll
        for (int i = 0; i < 16; ++i)
            __stcs(reinterpret_cast<u64*>(out + (size_t)(oout[i] + col)), a[i]);
    }
}

extern "C" void kernel_launch(void* const* d_in, const int* in_sizes, int n_in,
                              void* d_out, int out_size)
{
    const float* data    = (const float*)d_in[0];
    const float* angles  = (const float*)d_in[1];
    const float* biases  = (const float*)d_in[2];
    const int*   idx_in  = (const int*)d_in[3];
    const int*   idx_out = (const int*)d_in[4];
    float*       out     = (float*)d_out;

    const int N  = in_sizes[3];            // gathered rows (4096)
    const int B  = in_sizes[0] / N;        // row width (8192)
    const int R  = out_size / B;           // rows in out
    const int NB = N / 16;                 // butterfly row-blocks
    const int CG = (R + 15) / 16;          // copy row-groups

    // single launch:
    //   y in [0, NB)     : butterfly, CTA = 16 rows x 1024 cols (2 slices)
    //   y in [NB, NB+CG) : pass-through copy (x==0 only; scans idx_out)
    dim3 grid(B / 1024, NB + CG);
    butterfly_fused_kernel<<<grid, 256>>>(data, angles, biases, idx_in,
                                          idx_out, out, N, B, NB, R);
}